// round 7
// baseline (speedup 1.0000x reference)
#include <cuda_runtime.h>
#include <cuda_bf16.h>
#include <cstdint>

// BundleAdjustmentModel: project N points into V=64 camera views.
// out[v][n] = (u,v);  cam = R_v p + t_v;  u = -f*x/sz + cx, v = f*y/sz + cy.
// HBM-write-bound (256 MB out).
// Two kernels: (A) one block computes folded per-view params once into a
// __device__ global; (B) view-tiled mainloop (VG=8 views per block, 4 points
// per thread) reads params via a 2-instruction cooperative copy.
// Folding:  A = -f*R0, tA = -f*tx ; B = f*R1, tB = f*ty ; C = R2, tC = -depth
// safe-z via clamp: 1/safe_z == clamp(1/z, -1/eps, +1/eps)

#define V_VIEWS 64
#define VG 8            // views per block
#define PTS 4           // points per thread

// params: [v][12] = Ax Ay Az Bx | By Bz Cx Cy | Cz tA tB tC ; [768]=cx [769]=cy
__device__ __align__(16) float g_view_params[V_VIEWS * 12 + 4];

__global__ void setup_params_kernel(const float* __restrict__ euler,      // [V,3]
                                    const float* __restrict__ txy,        // [V,2]
                                    const float* __restrict__ tdepth,     // [V]
                                    const float* __restrict__ focal_raw,  // [1]
                                    const int*   __restrict__ cx_p,
                                    const int*   __restrict__ cy_p)
{
    const int v = threadIdx.x;
    if (v >= V_VIEWS) return;

    const float f = log1pf(expf(focal_raw[0])) + 50.0f;
    const float ex = euler[v * 3 + 0];
    const float ey = euler[v * 3 + 1];
    const float ez = euler[v * 3 + 2];
    float cxa = cosf(ex), sxa = sinf(ex);
    float cya = cosf(ey), sya = sinf(ey);
    float cza = cosf(ez), sza = sinf(ez);
    // R = Rx * Ry * Rz
    float R00 = cya * cza,                   R01 = -cya * sza,                  R02 = sya;
    float R10 = cxa * sza + sxa * sya * cza, R11 = cxa * cza - sxa * sya * sza, R12 = -sxa * cya;
    float R20 = sxa * sza - cxa * sya * cza, R21 = sxa * cza + cxa * sya * sza, R22 = cxa * cya;

    float* P = &g_view_params[v * 12];
    P[0] = -f * R00;  P[1] = -f * R01;  P[2] = -f * R02;
    P[3] =  f * R10;  P[4] =  f * R11;  P[5] =  f * R12;
    P[6] =  R20;      P[7] =  R21;      P[8] =  R22;
    P[9]  = -f * txy[v * 2 + 0];
    P[10] =  f * txy[v * 2 + 1];
    P[11] = -(log1pf(expf(tdepth[v])) + 0.25f);

    if (v == 0) {
        g_view_params[V_VIEWS * 12 + 0] = (float)cx_p[0];
        g_view_params[V_VIEWS * 12 + 1] = (float)cy_p[0];
    }
}

__global__ __launch_bounds__(128)
void bundle_project_kernel(const float* __restrict__ points,     // [N,3]
                           float* __restrict__ out,              // [V,N,2]
                           int n_pts,
                           int chunks)
{
    __shared__ __align__(16) float sP[VG][12];
    __shared__ float s_cx, s_cy;

    const int tid   = threadIdx.x;
    const int chunk = blockIdx.x % chunks;
    const int vbase = (blockIdx.x / chunks) * VG;

    if (tid < VG * 12) {
        reinterpret_cast<float*>(sP)[tid] = g_view_params[vbase * 12 + tid];
    } else if (tid == 96) {
        s_cx = g_view_params[V_VIEWS * 12 + 0];
    } else if (tid == 97) {
        s_cy = g_view_params[V_VIEWS * 12 + 1];
    }
    __syncthreads();

    const int i  = chunk * blockDim.x + tid;
    const int n0 = PTS * i;
    if (n0 >= n_pts) return;
    const bool full = (n0 + PTS) <= n_pts;

    // 4 points = 12 floats at byte offset 48*i -> three aligned LDG.128
    float px[PTS], py[PTS], pz[PTS];
    if (full) {
        const float4* pp = reinterpret_cast<const float4*>(points + (size_t)n0 * 3);
        float4 q0 = pp[0], q1 = pp[1], q2 = pp[2];
        px[0] = q0.x; py[0] = q0.y; pz[0] = q0.z;
        px[1] = q0.w; py[1] = q1.x; pz[1] = q1.y;
        px[2] = q1.z; py[2] = q1.w; pz[2] = q2.x;
        px[3] = q2.y; py[3] = q2.z; pz[3] = q2.w;
    } else {
        #pragma unroll
        for (int k = 0; k < PTS; k++) {
            if (n0 + k < n_pts) {
                px[k] = points[(size_t)(n0 + k) * 3 + 0];
                py[k] = points[(size_t)(n0 + k) * 3 + 1];
                pz[k] = points[(size_t)(n0 + k) * 3 + 2];
            } else {
                px[k] = py[k] = pz[k] = 0.f;
            }
        }
    }

    const float cxf = s_cx;
    const float cyf = s_cy;
    const float INV_CLAMP = 1.0f / 1e-4f;          // 1/Z_EPS
    const size_t view_stride = (size_t)n_pts * 2;  // floats per view slab

    float* base = out + ((size_t)vbase * n_pts + n0) * 2;

    #pragma unroll
    for (int v = 0; v < VG; v++) {
        const float4* pr = reinterpret_cast<const float4*>(&sP[v][0]);
        const float4 r0 = pr[0];   // Ax Ay Az Bx
        const float4 r1 = pr[1];   // By Bz Cx Cy
        const float4 r2 = pr[2];   // Cz tA tB tC

        float u[PTS], w[PTS];
        #pragma unroll
        for (int k = 0; k < PTS; k++) {
            float a = fmaf(r0.x, px[k], fmaf(r0.y, py[k], fmaf(r0.z, pz[k], r2.y)));
            float b = fmaf(r0.w, px[k], fmaf(r1.x, py[k], fmaf(r1.y, pz[k], r2.z)));
            float z = fmaf(r1.z, px[k], fmaf(r1.w, py[k], fmaf(r2.x, pz[k], r2.w)));
            float inv = __fdividef(1.0f, z);
            inv = fminf(fmaxf(inv, -INV_CLAMP), INV_CLAMP);
            u[k] = fmaf(a, inv, cxf);
            w[k] = fmaf(b, inv, cyf);
        }

        if (full) {
            __stcs(reinterpret_cast<float4*>(base),
                   make_float4(u[0], w[0], u[1], w[1]));
            __stcs(reinterpret_cast<float4*>(base) + 1,
                   make_float4(u[2], w[2], u[3], w[3]));
        } else {
            #pragma unroll
            for (int k = 0; k < PTS; k++) {
                if (n0 + k < n_pts) {
                    __stcs(reinterpret_cast<float2*>(base) + k,
                           make_float2(u[k], w[k]));
                }
            }
        }
        base += view_stride;
    }
}

extern "C" void kernel_launch(void* const* d_in, const int* in_sizes, int n_in,
                              void* d_out, int out_size) {
    const float* points    = (const float*)d_in[0];
    const float* euler     = (const float*)d_in[1];
    const float* txy       = (const float*)d_in[2];
    const float* tdepth    = (const float*)d_in[3];
    const float* focal_raw = (const float*)d_in[4];
    const int*   cx_p      = (const int*)d_in[5];
    const int*   cy_p      = (const int*)d_in[6];
    float*       out       = (float*)d_out;

    const int n_pts = in_sizes[0] / 3;            // points is [N,3]
    const int quads = (n_pts + PTS - 1) / PTS;    // 4 points per thread
    const int threads = 128;
    const int chunks = (quads + threads - 1) / threads;
    const int blocks = chunks * (V_VIEWS / VG);

    setup_params_kernel<<<1, V_VIEWS>>>(euler, txy, tdepth, focal_raw, cx_p, cy_p);
    bundle_project_kernel<<<blocks, threads>>>(points, out, n_pts, chunks);
}

// round 10
// speedup vs baseline: 1.5142x; 1.5142x over previous
#include <cuda_runtime.h>
#include <cuda_bf16.h>
#include <cstdint>

// BundleAdjustmentModel: project N points into V=64 camera views.
// out[v][n] = (u,v);  cam = R_v p + t_v;  u = -f*x/sz + cx, v = f*y/sz + cy.
// HBM-write-bound (256 MB out). Single persistent-wave kernel:
//   - 8 view-groups (VG=8 views each) x P blocks; grid = one resident wave.
//   - each block computes its 8 views' folded params ONCE, then grid-strides
//     over point chunks (prologue amortized ~7x vs one-chunk-per-block).
//   - mainloop: 2 points/thread, ONE warp-contiguous STG.128 per view
//     (512B burst). Warp store contiguity is load-bearing (R7: per-thread
//     widened stores stride 32B across the warp and double DRAM traffic).
// Folding:  A = -f*R0, tA = -f*tx ; B = f*R1, tB = f*ty ; C = R2, tC = -depth
// safe-z via clamp: 1/safe_z == clamp(1/z, -1/eps, +1/eps)

#define V_VIEWS 64
#define VG 8            // views per block

__global__ __launch_bounds__(128)
void bundle_project_kernel(const float* __restrict__ points,     // [N,3]
                           const float* __restrict__ euler,      // [V,3]
                           const float* __restrict__ txy,        // [V,2]
                           const float* __restrict__ tdepth,     // [V]
                           const float* __restrict__ focal_raw,  // [1]
                           const int*   __restrict__ cx_p,
                           const int*   __restrict__ cy_p,
                           float* __restrict__ out,              // [V,N,2]
                           int n_pts,
                           int chunks,
                           int P)        // blocks per view-group
{
    // 12 floats/view, 48B rows (16B-aligned) -> 3x LDS.128 broadcast per view.
    // layout: [Ax Ay Az Bx][By Bz Cx Cy][Cz tA tB tC]
    __shared__ __align__(16) float sP[VG][12];
    __shared__ float s_cx, s_cy;

    const int tid   = threadIdx.x;
    const int vbase = (blockIdx.x / P) * VG;
    const int c0    = blockIdx.x % P;

    if (tid < VG) {
        const int v = vbase + tid;
        const float f = log1pf(expf(focal_raw[0])) + 50.0f;
        const float ex = euler[v * 3 + 0];
        const float ey = euler[v * 3 + 1];
        const float ez = euler[v * 3 + 2];
        float cxa = cosf(ex), sxa = sinf(ex);
        float cya = cosf(ey), sya = sinf(ey);
        float cza = cosf(ez), sza = sinf(ez);
        // R = Rx * Ry * Rz
        float R00 = cya * cza,                   R01 = -cya * sza,                  R02 = sya;
        float R10 = cxa * sza + sxa * sya * cza, R11 = cxa * cza - sxa * sya * sza, R12 = -sxa * cya;
        float R20 = sxa * sza - cxa * sya * cza, R21 = sxa * cza + cxa * sya * sza, R22 = cxa * cya;

        sP[tid][0] = -f * R00;  sP[tid][1] = -f * R01;  sP[tid][2] = -f * R02;
        sP[tid][3] =  f * R10;  sP[tid][4] =  f * R11;  sP[tid][5] =  f * R12;
        sP[tid][6] =  R20;      sP[tid][7] =  R21;      sP[tid][8] =  R22;
        sP[tid][9]  = -f * txy[v * 2 + 0];                  // tA
        sP[tid][10] =  f * txy[v * 2 + 1];                  // tB
        const float d = tdepth[v];
        sP[tid][11] = -(log1pf(expf(d)) + 0.25f);           // tC = -depth
    }
    if (tid == 0) {
        s_cx = (float)cx_p[0];
        s_cy = (float)cy_p[0];
    }
    __syncthreads();

    const float cxf = s_cx;
    const float cyf = s_cy;
    const float INV_CLAMP = 1.0f / 1e-4f;          // 1/Z_EPS
    const size_t view_stride = (size_t)n_pts * 2;  // floats per view slab

    for (int chunk = c0; chunk < chunks; chunk += P) {
        const int i  = chunk * 128 + tid;
        const int n0 = 2 * i;
        if (n0 >= n_pts) break;                    // later chunks only larger
        const bool has2 = (n0 + 1) < n_pts;

        const float p0x = points[(size_t)n0 * 3 + 0];
        const float p0y = points[(size_t)n0 * 3 + 1];
        const float p0z = points[(size_t)n0 * 3 + 2];
        float p1x = 0.f, p1y = 0.f, p1z = 0.f;
        if (has2) {
            p1x = points[(size_t)(n0 + 1) * 3 + 0];
            p1y = points[(size_t)(n0 + 1) * 3 + 1];
            p1z = points[(size_t)(n0 + 1) * 3 + 2];
        }

        float* base = out + ((size_t)vbase * n_pts + n0) * 2;

        #pragma unroll
        for (int v = 0; v < VG; v++) {
            const float4* pr = reinterpret_cast<const float4*>(&sP[v][0]);
            const float4 r0 = pr[0];   // Ax Ay Az Bx
            const float4 r1 = pr[1];   // By Bz Cx Cy
            const float4 r2 = pr[2];   // Cz tA tB tC

            // point 0
            float a0 = fmaf(r0.x, p0x, fmaf(r0.y, p0y, fmaf(r0.z, p0z, r2.y)));
            float b0 = fmaf(r0.w, p0x, fmaf(r1.x, p0y, fmaf(r1.y, p0z, r2.z)));
            float z0 = fmaf(r1.z, p0x, fmaf(r1.w, p0y, fmaf(r2.x, p0z, r2.w)));
            float inv0 = __fdividef(1.0f, z0);
            inv0 = fminf(fmaxf(inv0, -INV_CLAMP), INV_CLAMP);
            float u0 = fmaf(a0, inv0, cxf);
            float w0 = fmaf(b0, inv0, cyf);

            // point 1
            float a1 = fmaf(r0.x, p1x, fmaf(r0.y, p1y, fmaf(r0.z, p1z, r2.y)));
            float b1 = fmaf(r0.w, p1x, fmaf(r1.x, p1y, fmaf(r1.y, p1z, r2.z)));
            float z1 = fmaf(r1.z, p1x, fmaf(r1.w, p1y, fmaf(r2.x, p1z, r2.w)));
            float inv1 = __fdividef(1.0f, z1);
            inv1 = fminf(fmaxf(inv1, -INV_CLAMP), INV_CLAMP);
            float u1 = fmaf(a1, inv1, cxf);
            float w1 = fmaf(b1, inv1, cyf);

            if (has2) {
                __stcs(reinterpret_cast<float4*>(base), make_float4(u0, w0, u1, w1));
            } else {
                __stcs(reinterpret_cast<float2*>(base), make_float2(u0, w0));
            }
            base += view_stride;
        }
    }
}

extern "C" void kernel_launch(void* const* d_in, const int* in_sizes, int n_in,
                              void* d_out, int out_size) {
    const float* points    = (const float*)d_in[0];
    const float* euler     = (const float*)d_in[1];
    const float* txy       = (const float*)d_in[2];
    const float* tdepth    = (const float*)d_in[3];
    const float* focal_raw = (const float*)d_in[4];
    const int*   cx_p      = (const int*)d_in[5];
    const int*   cy_p      = (const int*)d_in[6];
    float*       out       = (float*)d_out;

    const int n_pts = in_sizes[0] / 3;       // points is [N,3]
    const int pairs = (n_pts + 1) / 2;       // 2 points per thread
    const int threads = 128;
    const int chunks = (pairs + threads - 1) / threads;

    // One resident wave: 148 SMs x 16 CTAs(128thr) = 2368 blocks = 8 vgroups x 296
    int P = 296;
    if (P > chunks) P = chunks;
    const int blocks = P * (V_VIEWS / VG);

    bundle_project_kernel<<<blocks, threads>>>(points, euler, txy, tdepth,
                                               focal_raw, cx_p, cy_p,
                                               out, n_pts, chunks, P);
}